// round 17
// baseline (speedup 1.0000x reference)
#include <cuda_runtime.h>
#include <cuda_fp16.h>
#include <cstdint>
#include <cstddef>

#define NB 8
#define HW 4096
#define CI 256
#define DQ 64

// scratch (device globals -- no allocation allowed)
__device__ __half g_Qh[(size_t)NB * HW * DQ];     // fp16 Q, pre-scaled by sqrt(log2 e)
__device__ __half g_Eh[(size_t)NB * HW * HW];     // Eh[n][q][p] = half(2^(S - m[p] + 12))
__device__ __half g_Gt[(size_t)NB * CI * HW];     // G[n][c][p] = half(F[p][c] * 4096 * rZ[p])
__device__ float  g_rZ[NB * HW];                  // 4096 / sum_q Eh[q,p]
__device__ float  g_rn[NB * HW];                  // row norms of Q (log2-scaled space)
__device__ float  g_Mp[NB * 32];                  // per-block partial max norms
__device__ float  g_M[NB];                        // max row norm per batch

static __device__ __forceinline__ float ex2f(float x) {
    float y; asm("ex2.approx.ftz.f32 %0, %1;" : "=f"(y) : "f"(x));
    return y;
}
static __device__ __forceinline__ void mma16h(float c[4], unsigned a0, unsigned a1, unsigned a2,
                                              unsigned a3, unsigned b0, unsigned b1) {
    asm volatile(
        "mma.sync.aligned.m16n8k16.row.col.f32.f16.f16.f32 "
        "{%0,%1,%2,%3},{%4,%5,%6,%7},{%8,%9},{%0,%1,%2,%3};"
        : "+f"(c[0]), "+f"(c[1]), "+f"(c[2]), "+f"(c[3])
        : "r"(a0), "r"(a1), "r"(a2), "r"(a3), "r"(b0), "r"(b1));
}
static __device__ __forceinline__ void ldsm4(unsigned r[4], uint32_t a) {
    asm volatile("ldmatrix.sync.aligned.m8n8.x4.shared.b16 {%0,%1,%2,%3}, [%4];"
                 : "=r"(r[0]), "=r"(r[1]), "=r"(r[2]), "=r"(r[3]) : "r"(a));
}
static __device__ __forceinline__ void stsm4(uint32_t a, unsigned r0, unsigned r1,
                                             unsigned r2, unsigned r3) {
    asm volatile("stmatrix.sync.aligned.m8n8.x4.shared.b16 [%0], {%1,%2,%3,%4};"
                 :: "r"(a), "r"(r0), "r"(r1), "r"(r2), "r"(r3) : "memory");
}
static __device__ __forceinline__ uint32_t smem_u32(const void* p) {
    return (uint32_t)__cvta_generic_to_shared(p);
}
static __device__ __forceinline__ void cp16(uint32_t dst, const void* src) {
    asm volatile("cp.async.cg.shared.global [%0], [%1], 16;" :: "r"(dst), "l"(src) : "memory");
}

// ---------------------------------------------------------------------------
// K1: Q = (F @ W) * sqrt(log2 e), fp16 mma.
// ---------------------------------------------------------------------------
__global__ __launch_bounds__(256) void k_query(const float* __restrict__ F,
                                               const float* __restrict__ W) {
    __shared__ __half Fs[128][72];
    __shared__ __half Ws[64][72];
    const int tid = threadIdx.x, w = tid >> 5, lane = tid & 31;
    const int gid = lane >> 2, t4 = lane & 3;
    const int n = blockIdx.y, p0 = blockIdx.x * 128;
    const int wq = (w & 3) * 32, wd = (w >> 2) * 32;
    const float* Fb = F + ((size_t)n * HW + p0) * CI;

    const int l7 = lane & 7, lb3 = (lane >> 3) & 1, lb4 = lane >> 4;
    uint32_t aAddr[2], bAddr[2];
#pragma unroll
    for (int mt = 0; mt < 2; mt++)
        aAddr[mt] = smem_u32(&Fs[wq + mt * 16 + l7 + lb3 * 8][lb4 * 8]);
#pragma unroll
    for (int ntp = 0; ntp < 2; ntp++)
        bAddr[ntp] = smem_u32(&Ws[wd + ntp * 16 + l7 + lb4 * 8][lb3 * 8]);

    float acc[2][4][4] = {};
    for (int kc = 0; kc < 4; kc++) {
        __syncthreads();
#pragma unroll
        for (int i = 0; i < 8; i++) {
            int idx = tid + i * 256;
            int row = idx >> 4, c4 = (idx & 15) * 4;
            float4 v = *(const float4*)(Fb + (size_t)row * CI + kc * 64 + c4);
            *(__half2*)&Fs[row][c4]     = __floats2half2_rn(v.x, v.y);
            *(__half2*)&Fs[row][c4 + 2] = __floats2half2_rn(v.z, v.w);
        }
#pragma unroll
        for (int i = 0; i < 16; i++) {
            int idx = tid + i * 256;
            int ck = idx >> 6, d = idx & 63;
            Ws[d][ck] = __float2half(W[(size_t)(kc * 64 + ck) * DQ + d]);
        }
        __syncthreads();
#pragma unroll
        for (int kt = 0; kt < 4; kt++) {
            unsigned a[2][4], b[2][4];
            ldsm4(a[0], aAddr[0] + kt * 32);
            ldsm4(a[1], aAddr[1] + kt * 32);
            ldsm4(b[0], bAddr[0] + kt * 32);
            ldsm4(b[1], bAddr[1] + kt * 32);
#pragma unroll
            for (int mt = 0; mt < 2; mt++)
#pragma unroll
                for (int nt = 0; nt < 4; nt++)
                    mma16h(acc[mt][nt], a[mt][0], a[mt][1], a[mt][2], a[mt][3],
                           b[nt >> 1][(nt & 1) * 2], b[nt >> 1][(nt & 1) * 2 + 1]);
        }
    }
    const float s = 1.2011224087864498f;  // sqrt(log2 e)
    __half* Qb = g_Qh + (size_t)n * HW * DQ;
#pragma unroll
    for (int mt = 0; mt < 2; mt++)
#pragma unroll
        for (int nt = 0; nt < 4; nt++) {
            int p = p0 + wq + mt * 16 + gid;
            int d = wd + nt * 8 + 2 * t4;
            *(__half2*)(Qb + (size_t)p * DQ + d) =
                __floats2half2_rn(acc[mt][nt][0] * s, acc[mt][nt][1] * s);
            *(__half2*)(Qb + (size_t)(p + 8) * DQ + d) =
                __floats2half2_rn(acc[mt][nt][2] * s, acc[mt][nt][3] * s);
        }
}

// ---------------------------------------------------------------------------
// K1b: row norms of Q + per-block max.
// ---------------------------------------------------------------------------
__global__ __launch_bounds__(128) void k_norm1() {
    __shared__ float mx[128];
    const int n = blockIdx.y, p = blockIdx.x * 128 + threadIdx.x;
    const __half2* q = (const __half2*)(g_Qh + (size_t)(n * HW + p) * DQ);
    float s = 0.f;
#pragma unroll
    for (int i = 0; i < 32; i++) {
        float2 f = __half22float2(q[i]);
        s += f.x * f.x + f.y * f.y;
    }
    float rn = sqrtf(s);
    g_rn[n * HW + p] = rn;
    mx[threadIdx.x] = rn;
    __syncthreads();
    for (int d = 64; d > 0; d >>= 1) {
        if (threadIdx.x < d) mx[threadIdx.x] = fmaxf(mx[threadIdx.x], mx[threadIdx.x + d]);
        __syncthreads();
    }
    if (threadIdx.x == 0) g_Mp[n * 32 + blockIdx.x] = mx[0];
}
__global__ void k_norm2() {
    const int n = blockIdx.x;
    float m = g_Mp[n * 32 + threadIdx.x];
#pragma unroll
    for (int d = 16; d > 0; d >>= 1) m = fmaxf(m, __shfl_xor_sync(0xffffffffu, m, d));
    if (threadIdx.x == 0) g_M[n] = m;
}

// ---------------------------------------------------------------------------
// K2: block-per-p-tile, loop over all 32 q-tiles.
// Eh[q,p] = half(2^(S - rn[p]*M + 12)); Z accumulated in registers across the
// q-loop -> rZ written directly (k_zred eliminated).  Qp/ms loaded once.
// ---------------------------------------------------------------------------
#define K2_QP_OFF (128 * 72)
#define K2_ET_OFF (2 * 128 * 72)
#define K2_F32_OFF ((2 * 128 * 72 + 128 * 136) * 2)
#define K2_SMEM (K2_F32_OFF + (4 * 128 + 128) * 4)

__global__ __launch_bounds__(512, 2) void k_escore() {
    extern __shared__ char k2sm[];
    __half(*Qq)[72]  = (__half(*)[72])(k2sm);
    __half(*Qp)[72]  = (__half(*)[72])(k2sm + K2_QP_OFF * 2);
    __half(*Et)[136] = (__half(*)[136])(k2sm + K2_ET_OFF * 2);
    float* Zp        = (float*)(k2sm + K2_F32_OFF);
    float* ms        = Zp + 512;
    const int tid = threadIdx.x, w = tid >> 5, lane = tid & 31;
    const int gid = lane >> 2, t4 = lane & 3;
    const int pb = blockIdx.x, n = blockIdx.y;
    const int p0 = pb * 128;
    const int m0 = (w & 3) * 32, n0 = (w >> 2) * 32;
    const __half* Qh = g_Qh + (size_t)n * HW * DQ;

    // block-constant: Qp tile + shift table
#pragma unroll
    for (int i = 0; i < 2; i++) {
        int idx = tid + i * 512;
        int row = idx >> 3, ch = (idx & 7) * 8;
        *(uint4*)&Qp[row][ch] = *(const uint4*)(Qh + (size_t)(p0 + row) * DQ + ch);
    }
    if (tid < 128) ms[tid] = 12.f - g_rn[n * HW + p0 + tid] * g_M[n];

    const int l7 = lane & 7, lb3 = (lane >> 3) & 1, lb4 = lane >> 4;
    uint32_t aAddr[2], bAddr[2];
#pragma unroll
    for (int mt = 0; mt < 2; mt++)
        aAddr[mt] = smem_u32(&Qq[m0 + mt * 16 + l7 + lb3 * 8][lb4 * 8]);
#pragma unroll
    for (int ntp = 0; ntp < 2; ntp++)
        bAddr[ntp] = smem_u32(&Qp[n0 + ntp * 16 + l7 + lb4 * 8][lb3 * 8]);

    float cs0[4], cs1[4];
#pragma unroll
    for (int nt = 0; nt < 4; nt++) { cs0[nt] = 0.f; cs1[nt] = 0.f; }

    for (int qt = 0; qt < 32; qt++) {
        const int q0 = qt * 128;
        __syncthreads();  // prev iter's Et copy-out + Qq ldsm complete
#pragma unroll
        for (int i = 0; i < 2; i++) {
            int idx = tid + i * 512;
            int row = idx >> 3, ch = (idx & 7) * 8;
            *(uint4*)&Qq[row][ch] = *(const uint4*)(Qh + (size_t)(q0 + row) * DQ + ch);
        }
        __syncthreads();

        float acc[2][4][4] = {};
#pragma unroll
        for (int kt = 0; kt < 4; kt++) {
            unsigned a[2][4], b[2][4];
            ldsm4(a[0], aAddr[0] + kt * 32);
            ldsm4(a[1], aAddr[1] + kt * 32);
            ldsm4(b[0], bAddr[0] + kt * 32);
            ldsm4(b[1], bAddr[1] + kt * 32);
#pragma unroll
            for (int mt = 0; mt < 2; mt++)
#pragma unroll
                for (int nt = 0; nt < 4; nt++)
                    mma16h(acc[mt][nt], a[mt][0], a[mt][1], a[mt][2], a[mt][3],
                           b[nt >> 1][(nt & 1) * 2], b[nt >> 1][(nt & 1) * 2 + 1]);
        }

        unsigned uh[2][4][2];
#pragma unroll
        for (int nt = 0; nt < 4; nt++) {
            int cb = n0 + nt * 8 + 2 * t4;
            float s0 = ms[cb], s1 = ms[cb + 1];
#pragma unroll
            for (int mt = 0; mt < 2; mt++) {
                __half2 h0 = __floats2half2_rn(ex2f(acc[mt][nt][0] + s0),
                                               ex2f(acc[mt][nt][1] + s1));
                __half2 h1 = __floats2half2_rn(ex2f(acc[mt][nt][2] + s0),
                                               ex2f(acc[mt][nt][3] + s1));
                uh[mt][nt][0] = reinterpret_cast<unsigned&>(h0);
                uh[mt][nt][1] = reinterpret_cast<unsigned&>(h1);
                float2 f0 = __half22float2(h0), f1 = __half22float2(h1);
                cs0[nt] += f0.x + f1.x;
                cs1[nt] += f0.y + f1.y;
            }
        }
        {
            const int kk = lane >> 3, rr = lane & 7;
#pragma unroll
            for (int mt = 0; mt < 2; mt++)
#pragma unroll
                for (int np = 0; np < 2; np++) {
                    uint32_t ad = smem_u32(&Et[m0 + mt * 16 + (kk & 1) * 8 + rr]
                                              [n0 + np * 16 + (kk >> 1) * 8]);
                    stsm4(ad, uh[mt][2 * np][0], uh[mt][2 * np][1],
                          uh[mt][2 * np + 1][0], uh[mt][2 * np + 1][1]);
                }
        }
        __syncthreads();
        __half* Eb = g_Eh + (size_t)n * HW * HW + (size_t)q0 * HW + p0;
#pragma unroll
        for (int i = 0; i < 4; i++) {
            int idx = tid + i * 512;
            int row = idx >> 4, ch = (idx & 15) * 8;
            *(uint4*)(Eb + (size_t)row * HW + ch) = *(uint4*)&Et[row][ch];
        }
    }

    // final Z reduction -> rZ (fixed order: regs over q-loop, shfl, 4-slice sum)
#pragma unroll
    for (int nt = 0; nt < 4; nt++) {
        cs0[nt] += __shfl_xor_sync(0xffffffffu, cs0[nt], 4);
        cs0[nt] += __shfl_xor_sync(0xffffffffu, cs0[nt], 8);
        cs0[nt] += __shfl_xor_sync(0xffffffffu, cs0[nt], 16);
        cs1[nt] += __shfl_xor_sync(0xffffffffu, cs1[nt], 4);
        cs1[nt] += __shfl_xor_sync(0xffffffffu, cs1[nt], 8);
        cs1[nt] += __shfl_xor_sync(0xffffffffu, cs1[nt], 16);
    }
    if (lane < 4) {
#pragma unroll
        for (int nt = 0; nt < 4; nt++) {
            Zp[(w & 3) * 128 + n0 + nt * 8 + 2 * lane]     = cs0[nt];
            Zp[(w & 3) * 128 + n0 + nt * 8 + 2 * lane + 1] = cs1[nt];
        }
    }
    __syncthreads();
    if (tid < 128) {
        float z = Zp[tid] + Zp[128 + tid] + Zp[256 + tid] + Zp[384 + tid];
        g_rZ[n * HW + p0 + tid] = 4096.f / z;
    }
}

// ---------------------------------------------------------------------------
// K2c: G[c][p] = half(F[p][c] * rZ[p])  (transpose + fold, 32x32 tiles)
// ---------------------------------------------------------------------------
__global__ __launch_bounds__(256) void k_gt(const float* __restrict__ F) {
    __shared__ float t[32][33];
    __shared__ float rz[32];
    const int n = blockIdx.z, c0 = blockIdx.y * 32, p0 = blockIdx.x * 32;
    const int tx = threadIdx.x & 7, ty = threadIdx.x >> 3;
    const float* Fb = F + ((size_t)n * HW + p0) * CI;
    float4 v = *(const float4*)(Fb + (size_t)ty * CI + c0 + tx * 4);
    t[ty][tx * 4 + 0] = v.x; t[ty][tx * 4 + 1] = v.y;
    t[ty][tx * 4 + 2] = v.z; t[ty][tx * 4 + 3] = v.w;
    if (threadIdx.x < 32) rz[threadIdx.x] = g_rZ[n * HW + p0 + threadIdx.x];
    __syncthreads();
    const int cl = threadIdx.x >> 3, p4 = (threadIdx.x & 7) * 4;
    union { __half2 h[2]; uint2 u; } cv;
    cv.h[0] = __floats2half2_rn(t[p4 + 0][cl] * rz[p4 + 0], t[p4 + 1][cl] * rz[p4 + 1]);
    cv.h[1] = __floats2half2_rn(t[p4 + 2][cl] * rz[p4 + 2], t[p4 + 3][cl] * rz[p4 + 3]);
    *(uint2*)(g_Gt + ((size_t)n * CI + c0 + cl) * HW + p0 + p4) = cv.u;
}

// ---------------------------------------------------------------------------
// K3: PURE fp16 GEMM, FULL c=256 tile, 3-stage cp.async pipeline, fused
// output epilogue.  512 threads / 16 warps (4q x 4c), warp tile 32x64.
// Block 128q x 256c, k chunk 64.  Grid (q=32, n=8).
// ---------------------------------------------------------------------------
#define K5PAD 72
#define K5_STAGE (384 * K5PAD)              // halves per stage: E 128 rows + G 256 rows
#define K5_SMEM (3 * K5_STAGE * 2)          // 165888 bytes

__global__ __launch_bounds__(512, 1) void k_attf(const float* __restrict__ mask,
                                                 const float* __restrict__ ref,
                                                 float* __restrict__ out) {
    extern __shared__ __half smh[];
    __half* Es0 = smh;                       // stage: [E 128*72 | G 256*72]
    __half* Gs0 = smh + 128 * K5PAD;
    const int tid = threadIdx.x, w = tid >> 5, lane = tid & 31;
    const int gid = lane >> 2, t4 = lane & 3;
    const int q0 = blockIdx.x * 128, n = blockIdx.y;
    const int wq = (w & 3) * 32, wc = (w >> 2) * 64;
    const __half* Ebase = g_Eh + (size_t)n * HW * HW + (size_t)q0 * HW;
    const __half* Gbase = g_Gt + (size_t)n * CI * HW;

    const int erow = tid >> 3, lch = (tid & 7) * 8;  // erow in 0..63
    const int l7 = lane & 7, lb3 = (lane >> 3) & 1, lb4 = lane >> 4;
    uint32_t aAddr[2], bAddr[4];
#pragma unroll
    for (int mt = 0; mt < 2; mt++)
        aAddr[mt] = smem_u32(Es0 + (wq + mt * 16 + l7 + lb3 * 8) * K5PAD + lb4 * 8);
#pragma unroll
    for (int ntp = 0; ntp < 4; ntp++)
        bAddr[ntp] = smem_u32(Gs0 + (wc + ntp * 16 + l7 + lb4 * 8) * K5PAD + lb3 * 8);
    const uint32_t sdelta = K5_STAGE * 2;    // bytes between stages
    const uint32_t rdelta = 64 * K5PAD * 2;  // bytes between row r and r+64

    const uint32_t eDst = smem_u32(Es0 + erow * K5PAD + lch);
    const uint32_t gDst = smem_u32(Gs0 + erow * K5PAD + lch);
    const __half* eSrc0 = Ebase + (size_t)erow * HW + lch;
    const __half* eSrc1 = Ebase + (size_t)(erow + 64) * HW + lch;
    const __half* gSrc0 = Gbase + (size_t)erow * HW + lch;
    const __half* gSrc1 = Gbase + (size_t)(erow + 64) * HW + lch;
    const __half* gSrc2 = Gbase + (size_t)(erow + 128) * HW + lch;
    const __half* gSrc3 = Gbase + (size_t)(erow + 192) * HW + lch;

    float acc[2][8][4] = {};

    // prologue: chunks 0,1 into stages 0,1
#pragma unroll
    for (int s = 0; s < 2; s++) {
        const uint32_t so = s * sdelta;
        const int pp = s * 64;
        cp16(eDst + so, eSrc0 + pp);
        cp16(eDst + so + rdelta, eSrc1 + pp);
        cp16(gDst + so, gSrc0 + pp);
        cp16(gDst + so + rdelta, gSrc1 + pp);
        cp16(gDst + so + 2 * rdelta, gSrc2 + pp);
        cp16(gDst + so + 3 * rdelta, gSrc3 + pp);
        asm volatile("cp.async.commit_group;" ::: "memory");
    }

    int cur = 0, nxt = 2;
    for (int it = 0; it < 64; it++) {
        asm volatile("cp.async.wait_group 1;" ::: "memory");
        __syncthreads();
        if (it + 2 < 64) {
            const int pp = (it + 2) * 64;
            const uint32_t so = nxt * sdelta;
            cp16(eDst + so, eSrc0 + pp);
            cp16(eDst + so + rdelta, eSrc1 + pp);
            cp16(gDst + so, gSrc0 + pp);
            cp16(gDst + so + rdelta, gSrc1 + pp);
            cp16(gDst + so + 2 * rdelta, gSrc2 + pp);
            cp16(gDst + so + 3 * rdelta, gSrc3 + pp);
        }
        asm volatile("cp.async.commit_group;" ::: "memory");
        const uint32_t so = cur * sdelta;
#pragma unroll
        for (int kt = 0; kt < 4; kt++) {
            unsigned a[2][4], b[4][4];
            ldsm4(a[0], aAddr[0] + so + kt * 32);
            ldsm4(a[1], aAddr[1] + so + kt * 32);
#pragma unroll
            for (int ntp = 0; ntp < 4; ntp++)
                ldsm4(b[ntp], bAddr[ntp] + so + kt * 32);
#pragma unroll
            for (int mt = 0; mt < 2; mt++)
#pragma unroll
                for (int nt = 0; nt < 8; nt++)
                    mma16h(acc[mt][nt], a[mt][0], a[mt][1], a[mt][2], a[mt][3],
                           b[nt >> 1][(nt & 1) * 2], b[nt >> 1][(nt & 1) * 2 + 1]);
        }
        cur = (cur == 2) ? 0 : cur + 1;
        nxt = (nxt == 2) ? 0 : nxt + 1;
    }

    // Fused epilogue: r = c*16 + (q0>>8), cc = q & 255.
    const float inv = 1.f / 4096.f;
    const int qh8 = q0 >> 8;
    const float* refb = ref + (size_t)n * HW * CI;
    const float* maskb = mask + (size_t)n * HW;
    float* outb = out + (size_t)n * HW * (2 * CI);
#pragma unroll
    for (int mt = 0; mt < 2; mt++)
#pragma unroll
        for (int nt = 0; nt < 8; nt++)
#pragma unroll
            for (int i = 0; i < 2; i++)
#pragma unroll
                for (int j = 0; j < 2; j++) {
                    int q = q0 + wq + mt * 16 + gid + i * 8;
                    int c = wc + nt * 8 + 2 * t4 + j;
                    float a = acc[mt][nt][i * 2 + j] * inv;
                    int r = c * 16 + qh8;
                    int cc = q & 255;
                    float m = maskb[r];
                    float e = m * a + (1.f - m) * refb[(size_t)r * CI + cc];
                    size_t ob = (size_t)r * (2 * CI);
                    outb[ob + cc] = e;
                    outb[ob + CI + cc] = a;
                }
}

extern "C" void kernel_launch(void* const* d_in, const int* in_sizes, int n_in,
                              void* d_out, int out_size) {
    const float* mask = (const float*)d_in[0];
    const float* F    = (const float*)d_in[1];
    const float* ref  = (const float*)d_in[2];
    const float* W    = (const float*)d_in[3];
    float* out = (float*)d_out;
    (void)in_sizes; (void)n_in; (void)out_size;

    cudaFuncSetAttribute(k_escore, cudaFuncAttributeMaxDynamicSharedMemorySize, K2_SMEM);
    cudaFuncSetAttribute(k_attf,   cudaFuncAttributeMaxDynamicSharedMemorySize, K5_SMEM);

    k_query<<<dim3(32, 8), 256>>>(F, W);
    k_norm1<<<dim3(32, 8), 128>>>();
    k_norm2<<<8, 32>>>();
    k_escore<<<dim3(32, 8), 512, K2_SMEM>>>();
    k_gt<<<dim3(128, 8, 8), 256>>>(F);
    k_attf<<<dim3(32, 8), 512, K5_SMEM>>>(mask, ref, out);
}